// round 6
// baseline (speedup 1.0000x reference)
#include <cuda_runtime.h>
#include <math.h>

#define N_NODES 100000
#define B_GRAPHS 128
#define H 8
#define DC 256
#define DX 128   /* DE+4 */
#define DV 64
#define DOUT 124
#define S_SLICES 8
#define GB 4     /* graphs per block in k_qkq */

// ---- scratch (static device globals; no allocation) ----
__device__ __align__(16) float g_query[H * B_GRAPHS * DV];
__device__ __align__(16) float g_kq[H * B_GRAPHS * DX];
__device__ __align__(16) float g_u2[(size_t)N_NODES * H];   // [n][h]: u, then e
__device__ float g_inv[H * B_GRAPHS];
__device__ __align__(16) float g_part_xa[S_SLICES * H * B_GRAPHS * DX]; // 4 MB

// ---------------------------------------------------------------------------
__device__ __forceinline__ int lb_batch(const int* __restrict__ batch, int key) {
    int lo = 0, hi = N_NODES;
    while (lo < hi) {
        int mid = (lo + hi) >> 1;
        if (__ldg(batch + mid) < key) lo = mid + 1; else hi = mid;
    }
    return lo;
}

// ---------------------------------------------------------------------------
// Kernel 1: query + kq, 4 graphs per block. block=(h, graph-quad), 256 thr.
// ---------------------------------------------------------------------------
__global__ __launch_bounds__(256) void k_qkq(const float* __restrict__ context,
                                             const float* __restrict__ Wq,
                                             const float* __restrict__ Wk) {
    int h  = blockIdx.x >> 5;
    int gq = blockIdx.x & 31;
    int t = threadIdx.x;
    int part = t >> 6, v = t & 63;

    __shared__ float ctx_s[GB][DC];
    __shared__ float parts[4][GB][DV];
    __shared__ float q_s[GB][DV];

    for (int i = t; i < GB * DC; i += 256)
        ctx_s[i >> 8][i & 255] = context[(gq * GB + (i >> 8)) * DC + (i & 255)];
    __syncthreads();

    {
        float a0 = 0.f, a1 = 0.f, a2 = 0.f, a3 = 0.f;
        const float* wq = Wq + h * DC * DV + part * 64 * DV + v;
        const float* c0 = &ctx_s[0][part * 64];
        const float* c1 = &ctx_s[1][part * 64];
        const float* c2 = &ctx_s[2][part * 64];
        const float* c3 = &ctx_s[3][part * 64];
#pragma unroll 8
        for (int c = 0; c < 64; c++) {
            float wv = wq[c * DV];
            a0 = fmaf(c0[c], wv, a0);
            a1 = fmaf(c1[c], wv, a1);
            a2 = fmaf(c2[c], wv, a2);
            a3 = fmaf(c3[c], wv, a3);
        }
        parts[part][0][v] = a0;
        parts[part][1][v] = a1;
        parts[part][2][v] = a2;
        parts[part][3][v] = a3;
    }
    __syncthreads();
    {
        int b4 = t >> 6;
        float q = parts[0][b4][v] + parts[1][b4][v] + parts[2][b4][v] + parts[3][b4][v];
        q_s[b4][v] = q;
        g_query[(h * B_GRAPHS + gq * GB + b4) * DV + v] = q;
    }
    __syncthreads();

    // phase B: kq rows; warp w handles rows 16w..16w+15
    int w = t >> 5, lane = t & 31;
    float q00 = q_s[0][lane], q01 = q_s[0][lane + 32];
    float q10 = q_s[1][lane], q11 = q_s[1][lane + 32];
    float q20 = q_s[2][lane], q21 = q_s[2][lane + 32];
    float q30 = q_s[3][lane], q31 = q_s[3][lane + 32];

    const float* wk = Wk + h * DX * DV;
#pragma unroll 4
    for (int r = 0; r < 16; r++) {
        int e = w * 16 + r;
        float w0 = wk[e * DV + lane];
        float w1 = wk[e * DV + 32 + lane];
        float p0 = fmaf(w0, q00, w1 * q01);
        float p1 = fmaf(w0, q10, w1 * q11);
        float p2 = fmaf(w0, q20, w1 * q21);
        float p3 = fmaf(w0, q30, w1 * q31);
#pragma unroll
        for (int off = 16; off; off >>= 1) {
            p0 += __shfl_xor_sync(0xffffffffu, p0, off);
            p1 += __shfl_xor_sync(0xffffffffu, p1, off);
            p2 += __shfl_xor_sync(0xffffffffu, p2, off);
            p3 += __shfl_xor_sync(0xffffffffu, p3, off);
        }
        float pv = (lane & 2) ? ((lane & 1) ? p3 : p2) : ((lane & 1) ? p1 : p0);
        if (lane < 4)
            g_kq[(h * B_GRAPHS + gq * GB + lane) * DX + e] = pv * 0.125f;
    }
}

// ---------------------------------------------------------------------------
// Kernel 2: u[n][h] = x[n] . kq[h, g]. Barrier-free, smem-free.
// Warp processes 4 consecutive nodes per iteration; 62-shuffle butterfly
// ends with lane (b4 b3 b2 b1 b0) holding u(node=base+2*b3+b4,
// head=4*b0+2*b1+b2) -> one coalesced 128B STG per warp per 4 nodes.
// ---------------------------------------------------------------------------
__global__ __launch_bounds__(256, 3) void k_u(const float* __restrict__ x,
                                              const int* __restrict__ batch) {
    const int s = blockIdx.x;
    const int g = blockIdx.y;
    const int t = threadIdx.x;
    const int w = t >> 5;
    const int lane = t & 31;

    int s0 = lb_batch(batch, g);
    int s1 = lb_batch(batch, g + 1);
    int len = s1 - s0;
    int per = (len + S_SLICES - 1) / S_SLICES;
    int lo = s0 + s * per;
    int hi = min(lo + per, s1);

    float4 kq[H];
#pragma unroll
    for (int h = 0; h < H; h++)
        kq[h] = *(const float4*)(g_kq + (h * B_GRAPHS + g) * DX + lane * 4);

    const int b0 = lane & 1, b1 = (lane >> 1) & 1, b2 = (lane >> 2) & 1;
    const int b3 = (lane >> 3) & 1, b4v = (lane >> 4) & 1;
    const int kk = 2 * b3 + b4v;
    const int off32 = 16 * b3 + 8 * b4v + 4 * b0 + 2 * b1 + b2;

    const float4* xg = (const float4*)x;
    const float4 z = make_float4(0.f, 0.f, 0.f, 0.f);

    for (int base = lo + 4 * w; base < hi; base += 32) {
        float4 xv[4];
#pragma unroll
        for (int k = 0; k < 4; k++)
            xv[k] = (base + k < hi) ? xg[(size_t)(base + k) * 32 + lane] : z;

        float ra[4], rb[4];
#pragma unroll
        for (int k = 0; k < 4; k++) {
            float4 v = xv[k];
            float p0 = fmaf(kq[0].x, v.x, fmaf(kq[0].y, v.y, fmaf(kq[0].z, v.z, kq[0].w * v.w)));
            float p1 = fmaf(kq[1].x, v.x, fmaf(kq[1].y, v.y, fmaf(kq[1].z, v.z, kq[1].w * v.w)));
            float p2 = fmaf(kq[2].x, v.x, fmaf(kq[2].y, v.y, fmaf(kq[2].z, v.z, kq[2].w * v.w)));
            float p3 = fmaf(kq[3].x, v.x, fmaf(kq[3].y, v.y, fmaf(kq[3].z, v.z, kq[3].w * v.w)));
            float p4 = fmaf(kq[4].x, v.x, fmaf(kq[4].y, v.y, fmaf(kq[4].z, v.z, kq[4].w * v.w)));
            float p5 = fmaf(kq[5].x, v.x, fmaf(kq[5].y, v.y, fmaf(kq[5].z, v.z, kq[5].w * v.w)));
            float p6 = fmaf(kq[6].x, v.x, fmaf(kq[6].y, v.y, fmaf(kq[6].z, v.z, kq[6].w * v.w)));
            float p7 = fmaf(kq[7].x, v.x, fmaf(kq[7].y, v.y, fmaf(kq[7].z, v.z, kq[7].w * v.w)));
            // stage 1a: pair reduce (off=1)
            p0 += __shfl_xor_sync(0xffffffffu, p0, 1);
            p1 += __shfl_xor_sync(0xffffffffu, p1, 1);
            p2 += __shfl_xor_sync(0xffffffffu, p2, 1);
            p3 += __shfl_xor_sync(0xffffffffu, p3, 1);
            p4 += __shfl_xor_sync(0xffffffffu, p4, 1);
            p5 += __shfl_xor_sync(0xffffffffu, p5, 1);
            p6 += __shfl_xor_sync(0xffffffffu, p6, 1);
            p7 += __shfl_xor_sync(0xffffffffu, p7, 1);
            float q0 = b0 ? p4 : p0;   // head 4*b0 + 0
            float q1 = b0 ? p5 : p1;   // head 4*b0 + 1
            float q2 = b0 ? p6 : p2;   // head 4*b0 + 2
            float q3 = b0 ? p7 : p3;   // head 4*b0 + 3
            // stage 1b: quad reduce (off=2)
            q0 += __shfl_xor_sync(0xffffffffu, q0, 2);
            q1 += __shfl_xor_sync(0xffffffffu, q1, 2);
            q2 += __shfl_xor_sync(0xffffffffu, q2, 2);
            q3 += __shfl_xor_sync(0xffffffffu, q3, 2);
            ra[k] = b1 ? q2 : q0;      // head 4*b0 + 2*b1
            rb[k] = b1 ? q3 : q1;      // head 4*b0 + 2*b1 + 1
        }
        // stage 2: cross-quad reduce with value distribution
#pragma unroll
        for (int k = 0; k < 4; k++) {
            ra[k] += __shfl_xor_sync(0xffffffffu, ra[k], 4);
            rb[k] += __shfl_xor_sync(0xffffffffu, rb[k], 4);
        }
        float sv[4];
#pragma unroll
        for (int k = 0; k < 4; k++) sv[k] = b2 ? rb[k] : ra[k]; // head += b2
#pragma unroll
        for (int k = 0; k < 4; k++)
            sv[k] += __shfl_xor_sync(0xffffffffu, sv[k], 8);
        float t0 = b3 ? sv[2] : sv[0];   // node 2*b3 + 0
        float t1 = b3 ? sv[3] : sv[1];   // node 2*b3 + 1
        t0 += __shfl_xor_sync(0xffffffffu, t0, 16);
        t1 += __shfl_xor_sync(0xffffffffu, t1, 16);
        float uval = b4v ? t1 : t0;      // node 2*b3 + b4v = kk

        if (base + kk < hi) g_u2[(size_t)base * H + off32] = uval;
    }
}

// ---------------------------------------------------------------------------
// Kernel 3: exact per-(h,g) softmax over [n][h] array. Block per graph.
// t = (n32, h): coalesced. Two passes (max, then exp+sum); e stored in place.
// ---------------------------------------------------------------------------
__global__ __launch_bounds__(256) void k_softmax(const int* __restrict__ batch) {
    int g = blockIdx.x;
    int t = threadIdx.x;
    int n32 = t >> 3, hh = t & 7;
    int w = t >> 5, lane = t & 31;

    int s0 = lb_batch(batch, g);
    int s1 = lb_batch(batch, g + 1);

    __shared__ float red[8][9];
    __shared__ float bval[8];

    float m = -INFINITY;
    for (int base = s0; base < s1; base += 32) {
        int n = base + n32;
        if (n < s1) m = fmaxf(m, g_u2[(size_t)n * H + hh]);
    }
    m = fmaxf(m, __shfl_xor_sync(0xffffffffu, m, 8));
    m = fmaxf(m, __shfl_xor_sync(0xffffffffu, m, 16));
    if (lane < 8) red[w][lane] = m;
    __syncthreads();
    if (t < 8) {
        float mm = red[0][t];
#pragma unroll
        for (int ww = 1; ww < 8; ww++) mm = fmaxf(mm, red[ww][t]);
        bval[t] = mm;
    }
    __syncthreads();
    float mx = bval[hh];

    float ssum = 0.0f;
    for (int base = s0; base < s1; base += 32) {
        int n = base + n32;
        if (n < s1) {
            size_t idx = (size_t)n * H + hh;
            float e = __expf(g_u2[idx] - mx);
            g_u2[idx] = e;
            ssum += e;
        }
    }
    ssum += __shfl_xor_sync(0xffffffffu, ssum, 8);
    ssum += __shfl_xor_sync(0xffffffffu, ssum, 16);
    __syncthreads();
    if (lane < 8) red[w][lane] = ssum;
    __syncthreads();
    if (t < 8) {
        float sm = 0.0f;
#pragma unroll
        for (int ww = 0; ww < 8; ww++) sm += red[ww][t];
        g_inv[t * B_GRAPHS + g] = 1.0f / (sm + 1e-16f);
    }
}

// ---------------------------------------------------------------------------
// Kernel 4: xa slice partials = sum e[n][h] * x[n]. Pure LDG+FMA stream,
// no shuffles/barriers until block-end reduce. Profiled launch (#4).
// ---------------------------------------------------------------------------
__global__ __launch_bounds__(256, 3) void k_xa(const float* __restrict__ x,
                                               const int* __restrict__ batch) {
    const int s = blockIdx.x;
    const int g = blockIdx.y;
    const int t = threadIdx.x;
    const int w = t >> 5;
    const int lane = t & 31;

    int s0 = lb_batch(batch, g);
    int s1 = lb_batch(batch, g + 1);
    int len = s1 - s0;
    int per = (len + S_SLICES - 1) / S_SLICES;
    int lo = s0 + s * per;
    int hi = min(lo + per, s1);

    __shared__ __align__(16) float buf[H * H * DX];   // 32 KB

    float4 acc[H];
#pragma unroll
    for (int h = 0; h < H; h++) acc[h] = make_float4(0.f, 0.f, 0.f, 0.f);

    const float4* xg = (const float4*)x;
    const float4* eg = (const float4*)g_u2;

    for (int base = lo + 4 * w; base < hi; base += 32) {
#pragma unroll
        for (int k = 0; k < 4; k++) {
            int n = base + k;
            if (n < hi) {
                float4 xv  = xg[(size_t)n * 32 + lane];
                float4 alo = eg[(size_t)n * 2];
                float4 ahi = eg[(size_t)n * 2 + 1];
                acc[0].x = fmaf(alo.x, xv.x, acc[0].x); acc[0].y = fmaf(alo.x, xv.y, acc[0].y);
                acc[0].z = fmaf(alo.x, xv.z, acc[0].z); acc[0].w = fmaf(alo.x, xv.w, acc[0].w);
                acc[1].x = fmaf(alo.y, xv.x, acc[1].x); acc[1].y = fmaf(alo.y, xv.y, acc[1].y);
                acc[1].z = fmaf(alo.y, xv.z, acc[1].z); acc[1].w = fmaf(alo.y, xv.w, acc[1].w);
                acc[2].x = fmaf(alo.z, xv.x, acc[2].x); acc[2].y = fmaf(alo.z, xv.y, acc[2].y);
                acc[2].z = fmaf(alo.z, xv.z, acc[2].z); acc[2].w = fmaf(alo.z, xv.w, acc[2].w);
                acc[3].x = fmaf(alo.w, xv.x, acc[3].x); acc[3].y = fmaf(alo.w, xv.y, acc[3].y);
                acc[3].z = fmaf(alo.w, xv.z, acc[3].z); acc[3].w = fmaf(alo.w, xv.w, acc[3].w);
                acc[4].x = fmaf(ahi.x, xv.x, acc[4].x); acc[4].y = fmaf(ahi.x, xv.y, acc[4].y);
                acc[4].z = fmaf(ahi.x, xv.z, acc[4].z); acc[4].w = fmaf(ahi.x, xv.w, acc[4].w);
                acc[5].x = fmaf(ahi.y, xv.x, acc[5].x); acc[5].y = fmaf(ahi.y, xv.y, acc[5].y);
                acc[5].z = fmaf(ahi.y, xv.z, acc[5].z); acc[5].w = fmaf(ahi.y, xv.w, acc[5].w);
                acc[6].x = fmaf(ahi.z, xv.x, acc[6].x); acc[6].y = fmaf(ahi.z, xv.y, acc[6].y);
                acc[6].z = fmaf(ahi.z, xv.z, acc[6].z); acc[6].w = fmaf(ahi.z, xv.w, acc[6].w);
                acc[7].x = fmaf(ahi.w, xv.x, acc[7].x); acc[7].y = fmaf(ahi.w, xv.y, acc[7].y);
                acc[7].z = fmaf(ahi.w, xv.z, acc[7].z); acc[7].w = fmaf(ahi.w, xv.w, acc[7].w);
            }
        }
    }

#pragma unroll
    for (int h = 0; h < H; h++)
        *(float4*)(buf + ((w * H + h) * 32 + lane) * 4) = acc[h];
    __syncthreads();
    {
        int h = t >> 5;
        float4 sum = make_float4(0.f, 0.f, 0.f, 0.f);
#pragma unroll
        for (int ww = 0; ww < H; ww++) {
            float4 v = *(const float4*)(buf + ((ww * H + h) * 32 + lane) * 4);
            sum.x += v.x; sum.y += v.y; sum.z += v.z; sum.w += v.w;
        }
        *(float4*)(g_part_xa + (size_t)((s * H + h) * B_GRAPHS + g) * DX + lane * 4) = sum;
    }
}

// ---------------------------------------------------------------------------
// Kernel 5: combine + final projection. One block per graph, 1024 threads.
// ---------------------------------------------------------------------------
__global__ __launch_bounds__(1024) void k_cf(const float* __restrict__ Wv,
                                             const float* __restrict__ qcoef,
                                             const float* __restrict__ Wf,
                                             float* __restrict__ out) {
    int g = blockIdx.x;
    int t = threadIdx.x;
    int h = t >> 7, e = t & 127;

    __shared__ float xa_s[H][DX];
    __shared__ float hpart[H][DV];
    __shared__ float tot[DV];

    {
        float accv = 0.0f;
#pragma unroll
        for (int i = 0; i < S_SLICES; i++)
            accv += g_part_xa[(size_t)((i * H + h) * B_GRAPHS + g) * DX + e];
        xa_s[h][e] = accv * g_inv[h * B_GRAPHS + g];
    }
    __syncthreads();

    if (t < 512) {
        int h2 = t >> 6, v = t & 63;
        float accv = qcoef[0] * g_query[(h2 * B_GRAPHS + g) * DV + v];
        const float* wv = Wv + h2 * DX * DV + v;
        const float* xa = xa_s[h2];
#pragma unroll 16
        for (int e2 = 0; e2 < DX; e2++) accv = fmaf(xa[e2], wv[e2 * DV], accv);
        hpart[h2][v] = accv;
    }
    __syncthreads();

    if (t < DV) {
        float sum = 0.0f;
#pragma unroll
        for (int hh = 0; hh < H; hh++) sum += hpart[hh][t];
        tot[t] = sum;
    }
    __syncthreads();

    if (t < DOUT) {
        float accv = 0.0f;
#pragma unroll 16
        for (int v2 = 0; v2 < DV; v2++)
            accv = fmaf(tot[v2], Wf[v2 * DOUT + t], accv);
        out[g * DOUT + t] = accv;
    }
}

// ---------------------------------------------------------------------------
extern "C" void kernel_launch(void* const* d_in, const int* in_sizes, int n_in,
                              void* d_out, int out_size) {
    const float* x       = (const float*)d_in[0];
    // d_in[1] = edge_index (unused by the reference math)
    const int*   batch   = (const int*)d_in[2];
    const float* context = (const float*)d_in[3];
    const float* Wq      = (const float*)d_in[4];
    const float* Wk      = (const float*)d_in[5];
    const float* Wv      = (const float*)d_in[6];
    const float* qcoef   = (const float*)d_in[7];
    const float* Wf      = (const float*)d_in[8];
    float* out = (float*)d_out;

    dim3 sg(S_SLICES, B_GRAPHS);
    k_qkq<<<H * 32, 256>>>(context, Wq, Wk);       // 1
    k_u<<<sg, 256>>>(x, batch);                    // 2
    k_softmax<<<B_GRAPHS, 256>>>(batch);           // 3
    k_xa<<<sg, 256>>>(x, batch);                   // 4 -> profiled
    k_cf<<<B_GRAPHS, 1024>>>(Wv, qcoef, Wf, out);  // 5
}

// round 7
// speedup vs baseline: 1.0004x; 1.0004x over previous
#include <cuda_runtime.h>
#include <math.h>

#define N_NODES 100000
#define B_GRAPHS 128
#define H 8
#define DC 256
#define DX 128   /* DE+4 */
#define DV 64
#define DOUT 124
#define S_SLICES 8
#define GB 4     /* graphs per block in k_qkq */

// ---- scratch (static device globals; no allocation) ----
__device__ __align__(16) float g_query[H * B_GRAPHS * DV];
__device__ __align__(16) float g_kq[H * B_GRAPHS * DX];
__device__ __align__(16) float g_u2[(size_t)N_NODES * H];   // [n][h]: u, then e
__device__ float g_inv[H * B_GRAPHS];
__device__ __align__(16) float g_part_xa[S_SLICES * H * B_GRAPHS * DX]; // 4 MB

// ---------------------------------------------------------------------------
__device__ __forceinline__ int lb_batch(const int* __restrict__ batch, int key) {
    int lo = 0, hi = N_NODES;
    while (lo < hi) {
        int mid = (lo + hi) >> 1;
        if (__ldg(batch + mid) < key) lo = mid + 1; else hi = mid;
    }
    return lo;
}

// ---------------------------------------------------------------------------
// Kernel 1: query + kq, 4 graphs per block. block=(h, graph-quad), 256 thr.
// ---------------------------------------------------------------------------
__global__ __launch_bounds__(256) void k_qkq(const float* __restrict__ context,
                                             const float* __restrict__ Wq,
                                             const float* __restrict__ Wk) {
    int h  = blockIdx.x >> 5;
    int gq = blockIdx.x & 31;
    int t = threadIdx.x;
    int part = t >> 6, v = t & 63;

    __shared__ float ctx_s[GB][DC];
    __shared__ float parts[4][GB][DV];
    __shared__ float q_s[GB][DV];

    for (int i = t; i < GB * DC; i += 256)
        ctx_s[i >> 8][i & 255] = context[(gq * GB + (i >> 8)) * DC + (i & 255)];
    __syncthreads();

    {
        float a0 = 0.f, a1 = 0.f, a2 = 0.f, a3 = 0.f;
        const float* wq = Wq + h * DC * DV + part * 64 * DV + v;
        const float* c0 = &ctx_s[0][part * 64];
        const float* c1 = &ctx_s[1][part * 64];
        const float* c2 = &ctx_s[2][part * 64];
        const float* c3 = &ctx_s[3][part * 64];
#pragma unroll 8
        for (int c = 0; c < 64; c++) {
            float wv = wq[c * DV];
            a0 = fmaf(c0[c], wv, a0);
            a1 = fmaf(c1[c], wv, a1);
            a2 = fmaf(c2[c], wv, a2);
            a3 = fmaf(c3[c], wv, a3);
        }
        parts[part][0][v] = a0;
        parts[part][1][v] = a1;
        parts[part][2][v] = a2;
        parts[part][3][v] = a3;
    }
    __syncthreads();
    {
        int b4 = t >> 6;
        float q = parts[0][b4][v] + parts[1][b4][v] + parts[2][b4][v] + parts[3][b4][v];
        q_s[b4][v] = q;
        g_query[(h * B_GRAPHS + gq * GB + b4) * DV + v] = q;
    }
    __syncthreads();

    // phase B: kq rows; warp w handles rows 16w..16w+15
    int w = t >> 5, lane = t & 31;
    float q00 = q_s[0][lane], q01 = q_s[0][lane + 32];
    float q10 = q_s[1][lane], q11 = q_s[1][lane + 32];
    float q20 = q_s[2][lane], q21 = q_s[2][lane + 32];
    float q30 = q_s[3][lane], q31 = q_s[3][lane + 32];

    const float* wk = Wk + h * DX * DV;
#pragma unroll 4
    for (int r = 0; r < 16; r++) {
        int e = w * 16 + r;
        float w0 = wk[e * DV + lane];
        float w1 = wk[e * DV + 32 + lane];
        float p0 = fmaf(w0, q00, w1 * q01);
        float p1 = fmaf(w0, q10, w1 * q11);
        float p2 = fmaf(w0, q20, w1 * q21);
        float p3 = fmaf(w0, q30, w1 * q31);
#pragma unroll
        for (int off = 16; off; off >>= 1) {
            p0 += __shfl_xor_sync(0xffffffffu, p0, off);
            p1 += __shfl_xor_sync(0xffffffffu, p1, off);
            p2 += __shfl_xor_sync(0xffffffffu, p2, off);
            p3 += __shfl_xor_sync(0xffffffffu, p3, off);
        }
        float pv = (lane & 2) ? ((lane & 1) ? p3 : p2) : ((lane & 1) ? p1 : p0);
        if (lane < 4)
            g_kq[(h * B_GRAPHS + gq * GB + lane) * DX + e] = pv * 0.125f;
    }
}

// ---------------------------------------------------------------------------
// Kernel 2: u[n][h] = x[n] . kq[h, g]. Barrier-free, smem-free.
// Warp processes 4 consecutive nodes per iteration; 62-shuffle butterfly
// ends with lane (b4 b3 b2 b1 b0) holding u(node=base+2*b3+b4,
// head=4*b0+2*b1+b2) -> one coalesced 128B STG per warp per 4 nodes.
// ---------------------------------------------------------------------------
__global__ __launch_bounds__(256, 3) void k_u(const float* __restrict__ x,
                                              const int* __restrict__ batch) {
    const int s = blockIdx.x;
    const int g = blockIdx.y;
    const int t = threadIdx.x;
    const int w = t >> 5;
    const int lane = t & 31;

    int s0 = lb_batch(batch, g);
    int s1 = lb_batch(batch, g + 1);
    int len = s1 - s0;
    int per = (len + S_SLICES - 1) / S_SLICES;
    int lo = s0 + s * per;
    int hi = min(lo + per, s1);

    float4 kq[H];
#pragma unroll
    for (int h = 0; h < H; h++)
        kq[h] = *(const float4*)(g_kq + (h * B_GRAPHS + g) * DX + lane * 4);

    const int b0 = lane & 1, b1 = (lane >> 1) & 1, b2 = (lane >> 2) & 1;
    const int b3 = (lane >> 3) & 1, b4v = (lane >> 4) & 1;
    const int kk = 2 * b3 + b4v;
    const int off32 = 16 * b3 + 8 * b4v + 4 * b0 + 2 * b1 + b2;

    const float4* xg = (const float4*)x;
    const float4 z = make_float4(0.f, 0.f, 0.f, 0.f);

    for (int base = lo + 4 * w; base < hi; base += 32) {
        float4 xv[4];
#pragma unroll
        for (int k = 0; k < 4; k++)
            xv[k] = (base + k < hi) ? xg[(size_t)(base + k) * 32 + lane] : z;

        float ra[4], rb[4];
#pragma unroll
        for (int k = 0; k < 4; k++) {
            float4 v = xv[k];
            float p0 = fmaf(kq[0].x, v.x, fmaf(kq[0].y, v.y, fmaf(kq[0].z, v.z, kq[0].w * v.w)));
            float p1 = fmaf(kq[1].x, v.x, fmaf(kq[1].y, v.y, fmaf(kq[1].z, v.z, kq[1].w * v.w)));
            float p2 = fmaf(kq[2].x, v.x, fmaf(kq[2].y, v.y, fmaf(kq[2].z, v.z, kq[2].w * v.w)));
            float p3 = fmaf(kq[3].x, v.x, fmaf(kq[3].y, v.y, fmaf(kq[3].z, v.z, kq[3].w * v.w)));
            float p4 = fmaf(kq[4].x, v.x, fmaf(kq[4].y, v.y, fmaf(kq[4].z, v.z, kq[4].w * v.w)));
            float p5 = fmaf(kq[5].x, v.x, fmaf(kq[5].y, v.y, fmaf(kq[5].z, v.z, kq[5].w * v.w)));
            float p6 = fmaf(kq[6].x, v.x, fmaf(kq[6].y, v.y, fmaf(kq[6].z, v.z, kq[6].w * v.w)));
            float p7 = fmaf(kq[7].x, v.x, fmaf(kq[7].y, v.y, fmaf(kq[7].z, v.z, kq[7].w * v.w)));
            // stage 1a: pair reduce (off=1)
            p0 += __shfl_xor_sync(0xffffffffu, p0, 1);
            p1 += __shfl_xor_sync(0xffffffffu, p1, 1);
            p2 += __shfl_xor_sync(0xffffffffu, p2, 1);
            p3 += __shfl_xor_sync(0xffffffffu, p3, 1);
            p4 += __shfl_xor_sync(0xffffffffu, p4, 1);
            p5 += __shfl_xor_sync(0xffffffffu, p5, 1);
            p6 += __shfl_xor_sync(0xffffffffu, p6, 1);
            p7 += __shfl_xor_sync(0xffffffffu, p7, 1);
            float q0 = b0 ? p4 : p0;   // head 4*b0 + 0
            float q1 = b0 ? p5 : p1;   // head 4*b0 + 1
            float q2 = b0 ? p6 : p2;   // head 4*b0 + 2
            float q3 = b0 ? p7 : p3;   // head 4*b0 + 3
            // stage 1b: quad reduce (off=2)
            q0 += __shfl_xor_sync(0xffffffffu, q0, 2);
            q1 += __shfl_xor_sync(0xffffffffu, q1, 2);
            q2 += __shfl_xor_sync(0xffffffffu, q2, 2);
            q3 += __shfl_xor_sync(0xffffffffu, q3, 2);
            ra[k] = b1 ? q2 : q0;      // head 4*b0 + 2*b1
            rb[k] = b1 ? q3 : q1;      // head 4*b0 + 2*b1 + 1
        }
        // stage 2: cross-quad reduce with value distribution
#pragma unroll
        for (int k = 0; k < 4; k++) {
            ra[k] += __shfl_xor_sync(0xffffffffu, ra[k], 4);
            rb[k] += __shfl_xor_sync(0xffffffffu, rb[k], 4);
        }
        float sv[4];
#pragma unroll
        for (int k = 0; k < 4; k++) sv[k] = b2 ? rb[k] : ra[k]; // head += b2
#pragma unroll
        for (int k = 0; k < 4; k++)
            sv[k] += __shfl_xor_sync(0xffffffffu, sv[k], 8);
        float t0 = b3 ? sv[2] : sv[0];   // node 2*b3 + 0
        float t1 = b3 ? sv[3] : sv[1];   // node 2*b3 + 1
        t0 += __shfl_xor_sync(0xffffffffu, t0, 16);
        t1 += __shfl_xor_sync(0xffffffffu, t1, 16);
        float uval = b4v ? t1 : t0;      // node 2*b3 + b4v = kk

        if (base + kk < hi) g_u2[(size_t)base * H + off32] = uval;
    }
}

// ---------------------------------------------------------------------------
// Kernel 3: exact per-(h,g) softmax over [n][h] array. Block per graph.
// t = (n32, h): coalesced. Two passes (max, then exp+sum); e stored in place.
// ---------------------------------------------------------------------------
__global__ __launch_bounds__(256) void k_softmax(const int* __restrict__ batch) {
    int g = blockIdx.x;
    int t = threadIdx.x;
    int n32 = t >> 3, hh = t & 7;
    int w = t >> 5, lane = t & 31;

    int s0 = lb_batch(batch, g);
    int s1 = lb_batch(batch, g + 1);

    __shared__ float red[8][9];
    __shared__ float bval[8];

    float m = -INFINITY;
    for (int base = s0; base < s1; base += 32) {
        int n = base + n32;
        if (n < s1) m = fmaxf(m, g_u2[(size_t)n * H + hh]);
    }
    m = fmaxf(m, __shfl_xor_sync(0xffffffffu, m, 8));
    m = fmaxf(m, __shfl_xor_sync(0xffffffffu, m, 16));
    if (lane < 8) red[w][lane] = m;
    __syncthreads();
    if (t < 8) {
        float mm = red[0][t];
#pragma unroll
        for (int ww = 1; ww < 8; ww++) mm = fmaxf(mm, red[ww][t]);
        bval[t] = mm;
    }
    __syncthreads();
    float mx = bval[hh];

    float ssum = 0.0f;
    for (int base = s0; base < s1; base += 32) {
        int n = base + n32;
        if (n < s1) {
            size_t idx = (size_t)n * H + hh;
            float e = __expf(g_u2[idx] - mx);
            g_u2[idx] = e;
            ssum += e;
        }
    }
    ssum += __shfl_xor_sync(0xffffffffu, ssum, 8);
    ssum += __shfl_xor_sync(0xffffffffu, ssum, 16);
    __syncthreads();
    if (lane < 8) red[w][lane] = ssum;
    __syncthreads();
    if (t < 8) {
        float sm = 0.0f;
#pragma unroll
        for (int ww = 0; ww < 8; ww++) sm += red[ww][t];
        g_inv[t * B_GRAPHS + g] = 1.0f / (sm + 1e-16f);
    }
}

// ---------------------------------------------------------------------------
// Kernel 4: xa slice partials = sum e[n][h] * x[n]. Pure LDG+FMA stream,
// no shuffles/barriers until block-end reduce. Profiled launch (#4).
// ---------------------------------------------------------------------------
__global__ __launch_bounds__(256, 3) void k_xa(const float* __restrict__ x,
                                               const int* __restrict__ batch) {
    const int s = blockIdx.x;
    const int g = blockIdx.y;
    const int t = threadIdx.x;
    const int w = t >> 5;
    const int lane = t & 31;

    int s0 = lb_batch(batch, g);
    int s1 = lb_batch(batch, g + 1);
    int len = s1 - s0;
    int per = (len + S_SLICES - 1) / S_SLICES;
    int lo = s0 + s * per;
    int hi = min(lo + per, s1);

    __shared__ __align__(16) float buf[H * H * DX];   // 32 KB

    float4 acc[H];
#pragma unroll
    for (int h = 0; h < H; h++) acc[h] = make_float4(0.f, 0.f, 0.f, 0.f);

    const float4* xg = (const float4*)x;
    const float4* eg = (const float4*)g_u2;

    for (int base = lo + 4 * w; base < hi; base += 32) {
#pragma unroll
        for (int k = 0; k < 4; k++) {
            int n = base + k;
            if (n < hi) {
                float4 xv  = xg[(size_t)n * 32 + lane];
                float4 alo = eg[(size_t)n * 2];
                float4 ahi = eg[(size_t)n * 2 + 1];
                acc[0].x = fmaf(alo.x, xv.x, acc[0].x); acc[0].y = fmaf(alo.x, xv.y, acc[0].y);
                acc[0].z = fmaf(alo.x, xv.z, acc[0].z); acc[0].w = fmaf(alo.x, xv.w, acc[0].w);
                acc[1].x = fmaf(alo.y, xv.x, acc[1].x); acc[1].y = fmaf(alo.y, xv.y, acc[1].y);
                acc[1].z = fmaf(alo.y, xv.z, acc[1].z); acc[1].w = fmaf(alo.y, xv.w, acc[1].w);
                acc[2].x = fmaf(alo.z, xv.x, acc[2].x); acc[2].y = fmaf(alo.z, xv.y, acc[2].y);
                acc[2].z = fmaf(alo.z, xv.z, acc[2].z); acc[2].w = fmaf(alo.z, xv.w, acc[2].w);
                acc[3].x = fmaf(alo.w, xv.x, acc[3].x); acc[3].y = fmaf(alo.w, xv.y, acc[3].y);
                acc[3].z = fmaf(alo.w, xv.z, acc[3].z); acc[3].w = fmaf(alo.w, xv.w, acc[3].w);
                acc[4].x = fmaf(ahi.x, xv.x, acc[4].x); acc[4].y = fmaf(ahi.x, xv.y, acc[4].y);
                acc[4].z = fmaf(ahi.x, xv.z, acc[4].z); acc[4].w = fmaf(ahi.x, xv.w, acc[4].w);
                acc[5].x = fmaf(ahi.y, xv.x, acc[5].x); acc[5].y = fmaf(ahi.y, xv.y, acc[5].y);
                acc[5].z = fmaf(ahi.y, xv.z, acc[5].z); acc[5].w = fmaf(ahi.y, xv.w, acc[5].w);
                acc[6].x = fmaf(ahi.z, xv.x, acc[6].x); acc[6].y = fmaf(ahi.z, xv.y, acc[6].y);
                acc[6].z = fmaf(ahi.z, xv.z, acc[6].z); acc[6].w = fmaf(ahi.z, xv.w, acc[6].w);
                acc[7].x = fmaf(ahi.w, xv.x, acc[7].x); acc[7].y = fmaf(ahi.w, xv.y, acc[7].y);
                acc[7].z = fmaf(ahi.w, xv.z, acc[7].z); acc[7].w = fmaf(ahi.w, xv.w, acc[7].w);
            }
        }
    }

#pragma unroll
    for (int h = 0; h < H; h++)
        *(float4*)(buf + ((w * H + h) * 32 + lane) * 4) = acc[h];
    __syncthreads();
    {
        int h = t >> 5;
        float4 sum = make_float4(0.f, 0.f, 0.f, 0.f);
#pragma unroll
        for (int ww = 0; ww < H; ww++) {
            float4 v = *(const float4*)(buf + ((ww * H + h) * 32 + lane) * 4);
            sum.x += v.x; sum.y += v.y; sum.z += v.z; sum.w += v.w;
        }
        *(float4*)(g_part_xa + (size_t)((s * H + h) * B_GRAPHS + g) * DX + lane * 4) = sum;
    }
}

// ---------------------------------------------------------------------------
// Kernel 5: combine + final projection. One block per graph, 1024 threads.
// ---------------------------------------------------------------------------
__global__ __launch_bounds__(1024) void k_cf(const float* __restrict__ Wv,
                                             const float* __restrict__ qcoef,
                                             const float* __restrict__ Wf,
                                             float* __restrict__ out) {
    int g = blockIdx.x;
    int t = threadIdx.x;
    int h = t >> 7, e = t & 127;

    __shared__ float xa_s[H][DX];
    __shared__ float hpart[H][DV];
    __shared__ float tot[DV];

    {
        float accv = 0.0f;
#pragma unroll
        for (int i = 0; i < S_SLICES; i++)
            accv += g_part_xa[(size_t)((i * H + h) * B_GRAPHS + g) * DX + e];
        xa_s[h][e] = accv * g_inv[h * B_GRAPHS + g];
    }
    __syncthreads();

    if (t < 512) {
        int h2 = t >> 6, v = t & 63;
        float accv = qcoef[0] * g_query[(h2 * B_GRAPHS + g) * DV + v];
        const float* wv = Wv + h2 * DX * DV + v;
        const float* xa = xa_s[h2];
#pragma unroll 16
        for (int e2 = 0; e2 < DX; e2++) accv = fmaf(xa[e2], wv[e2 * DV], accv);
        hpart[h2][v] = accv;
    }
    __syncthreads();

    if (t < DV) {
        float sum = 0.0f;
#pragma unroll
        for (int hh = 0; hh < H; hh++) sum += hpart[hh][t];
        tot[t] = sum;
    }
    __syncthreads();

    if (t < DOUT) {
        float accv = 0.0f;
#pragma unroll 16
        for (int v2 = 0; v2 < DV; v2++)
            accv = fmaf(tot[v2], Wf[v2 * DOUT + t], accv);
        out[g * DOUT + t] = accv;
    }
}

// ---------------------------------------------------------------------------
extern "C" void kernel_launch(void* const* d_in, const int* in_sizes, int n_in,
                              void* d_out, int out_size) {
    const float* x       = (const float*)d_in[0];
    // d_in[1] = edge_index (unused by the reference math)
    const int*   batch   = (const int*)d_in[2];
    const float* context = (const float*)d_in[3];
    const float* Wq      = (const float*)d_in[4];
    const float* Wk      = (const float*)d_in[5];
    const float* Wv      = (const float*)d_in[6];
    const float* qcoef   = (const float*)d_in[7];
    const float* Wf      = (const float*)d_in[8];
    float* out = (float*)d_out;

    dim3 sg(S_SLICES, B_GRAPHS);
    k_qkq<<<H * 32, 256>>>(context, Wq, Wk);       // 1
    k_u<<<sg, 256>>>(x, batch);                    // 2
    k_softmax<<<B_GRAPHS, 256>>>(batch);           // 3
    k_xa<<<sg, 256>>>(x, batch);                   // 4 -> profiled
    k_cf<<<B_GRAPHS, 1024>>>(Wv, qcoef, Wf, out);  // 5
}

// round 8
// speedup vs baseline: 1.2816x; 1.2811x over previous
#include <cuda_runtime.h>
#include <math.h>

#define N_NODES 100000
#define B_GRAPHS 128
#define H 8
#define DC 256
#define DX 128   /* DE+4 */
#define DV 64
#define DOUT 124
#define S_SLICES 4
#define GB 4

// ---- scratch (static device globals; no allocation) ----
__device__ __align__(16) float g_query[H * B_GRAPHS * DV];
__device__ __align__(16) float g_kq[H * B_GRAPHS * DX];
__device__ __align__(16) float g_part_xa[S_SLICES * H * B_GRAPHS * DX]; // 2 MB
__device__ float g_part_m[S_SLICES * H * B_GRAPHS];
__device__ float g_part_s[S_SLICES * H * B_GRAPHS];

// ---------------------------------------------------------------------------
__device__ __forceinline__ int lb_batch(const int* __restrict__ batch, int key) {
    int lo = 0, hi = N_NODES;
    while (lo < hi) {
        int mid = (lo + hi) >> 1;
        if (__ldg(batch + mid) < key) lo = mid + 1; else hi = mid;
    }
    return lo;
}

// ---------------------------------------------------------------------------
// Kernel 1: query + kq, 4 graphs per block. block=(h, graph-quad), 256 thr.
// ---------------------------------------------------------------------------
__global__ __launch_bounds__(256) void k_qkq(const float* __restrict__ context,
                                             const float* __restrict__ Wq,
                                             const float* __restrict__ Wk) {
    int h  = blockIdx.x >> 5;
    int gq = blockIdx.x & 31;
    int t = threadIdx.x;
    int part = t >> 6, v = t & 63;

    __shared__ float ctx_s[GB][DC];
    __shared__ float parts[4][GB][DV];
    __shared__ float q_s[GB][DV];

    for (int i = t; i < GB * DC; i += 256)
        ctx_s[i >> 8][i & 255] = context[(gq * GB + (i >> 8)) * DC + (i & 255)];
    __syncthreads();

    {
        float a0 = 0.f, a1 = 0.f, a2 = 0.f, a3 = 0.f;
        const float* wq = Wq + h * DC * DV + part * 64 * DV + v;
        const float* c0 = &ctx_s[0][part * 64];
        const float* c1 = &ctx_s[1][part * 64];
        const float* c2 = &ctx_s[2][part * 64];
        const float* c3 = &ctx_s[3][part * 64];
#pragma unroll 8
        for (int c = 0; c < 64; c++) {
            float wv = wq[c * DV];
            a0 = fmaf(c0[c], wv, a0);
            a1 = fmaf(c1[c], wv, a1);
            a2 = fmaf(c2[c], wv, a2);
            a3 = fmaf(c3[c], wv, a3);
        }
        parts[part][0][v] = a0;
        parts[part][1][v] = a1;
        parts[part][2][v] = a2;
        parts[part][3][v] = a3;
    }
    __syncthreads();
    {
        int b4 = t >> 6;
        float q = parts[0][b4][v] + parts[1][b4][v] + parts[2][b4][v] + parts[3][b4][v];
        q_s[b4][v] = q;
        g_query[(h * B_GRAPHS + gq * GB + b4) * DV + v] = q;
    }
    __syncthreads();

    int w = t >> 5, lane = t & 31;
    float q00 = q_s[0][lane], q01 = q_s[0][lane + 32];
    float q10 = q_s[1][lane], q11 = q_s[1][lane + 32];
    float q20 = q_s[2][lane], q21 = q_s[2][lane + 32];
    float q30 = q_s[3][lane], q31 = q_s[3][lane + 32];

    const float* wk = Wk + h * DX * DV;
#pragma unroll 4
    for (int r = 0; r < 16; r++) {
        int e = w * 16 + r;
        float w0 = wk[e * DV + lane];
        float w1 = wk[e * DV + 32 + lane];
        float p0 = fmaf(w0, q00, w1 * q01);
        float p1 = fmaf(w0, q10, w1 * q11);
        float p2 = fmaf(w0, q20, w1 * q21);
        float p3 = fmaf(w0, q30, w1 * q31);
#pragma unroll
        for (int off = 16; off; off >>= 1) {
            p0 += __shfl_xor_sync(0xffffffffu, p0, off);
            p1 += __shfl_xor_sync(0xffffffffu, p1, off);
            p2 += __shfl_xor_sync(0xffffffffu, p2, off);
            p3 += __shfl_xor_sync(0xffffffffu, p3, off);
        }
        float pv = (lane & 2) ? ((lane & 1) ? p3 : p2) : ((lane & 1) ? p1 : p0);
        if (lane < 4)
            g_kq[(h * B_GRAPHS + gq * GB + lane) * DX + e] = pv * 0.125f;
    }
}

// ---------------------------------------------------------------------------
// Kernel 2 (fused, head-split): warps 0-3 = heads 0-3, warps 4-7 = heads 4-7.
// Warp (grp,wi) owns chunk nodes [8*wi, 8*wi+8) for its 4 heads.
// kq + xa accumulators in registers (4 heads each); x re-read in xa-phase
// (L1-resident). Online softmax finalized per chunk by warp h (head h).
// ---------------------------------------------------------------------------
__global__ __launch_bounds__(256, 3) void k_fused(const float* __restrict__ x,
                                                  const int* __restrict__ batch) {
    const int s = blockIdx.x;
    const int g = blockIdx.y;
    const int t = threadIdx.x;
    const int w = t >> 5;
    const int lane = t & 31;
    const int grp = w >> 2;          // head group: 0 -> heads 0-3, 1 -> heads 4-7
    const int wi  = w & 3;           // node octet within chunk

    const int b0 = lane & 1, b1 = (lane >> 1) & 1, b2 = (lane >> 2) & 1;
    const int b3 = (lane >> 3) & 1, b4v = (lane >> 4) & 1;

    __shared__ float us[32 * 9];     // [node][head], stride 9 (conflict-free read)
    __shared__ float es[H * 33];     // [head][node], stride 33
    __shared__ float sc[H];
    __shared__ __align__(16) float buf[H * 4 * DX];  // 16 KB: [grp*16+wi*4+j][e]

    int s0 = lb_batch(batch, g);
    int s1 = lb_batch(batch, g + 1);
    int len = s1 - s0;
    int per = (len + S_SLICES - 1) / S_SLICES;
    int lo = s0 + s * per;
    int hi = min(lo + per, s1);

    float4 kq[4];
#pragma unroll
    for (int j = 0; j < 4; j++)
        kq[j] = *(const float4*)(g_kq + ((grp * 4 + j) * B_GRAPHS + g) * DX + lane * 4);

    float4 acc[4];
#pragma unroll
    for (int j = 0; j < 4; j++) acc[j] = make_float4(0.f, 0.f, 0.f, 0.f);

    float m_run = -INFINITY, s_run = 0.0f;   // warp w's state for head w

    const float4* xg = (const float4*)x;
    const float4 z = make_float4(0.f, 0.f, 0.f, 0.f);
    const int nodebase = wi * 8;
    // final butterfly lane mapping: node = 4*b4 + 2*b3 + b2, head_l = 2*b1 + b0
    const int us_idx = (nodebase + 4 * b4v + 2 * b3 + b2) * 9 + grp * 4 + 2 * b1 + b0;

    for (int c0 = lo; c0 < hi; c0 += 32) {
        int valid = min(32, hi - c0);

        // ---- u-phase: 8 nodes x 4 heads per warp
        float rv[8];
#pragma unroll
        for (int k = 0; k < 8; k++) {
            int n = c0 + nodebase + k;
            float4 xv = (n < hi) ? xg[(size_t)n * 32 + lane] : z;
            float p0 = fmaf(kq[0].x, xv.x, fmaf(kq[0].y, xv.y, fmaf(kq[0].z, xv.z, kq[0].w * xv.w)));
            float p1 = fmaf(kq[1].x, xv.x, fmaf(kq[1].y, xv.y, fmaf(kq[1].z, xv.z, kq[1].w * xv.w)));
            float p2 = fmaf(kq[2].x, xv.x, fmaf(kq[2].y, xv.y, fmaf(kq[2].z, xv.z, kq[2].w * xv.w)));
            float p3 = fmaf(kq[3].x, xv.x, fmaf(kq[3].y, xv.y, fmaf(kq[3].z, xv.z, kq[3].w * xv.w)));
            p0 += __shfl_xor_sync(0xffffffffu, p0, 1);
            p1 += __shfl_xor_sync(0xffffffffu, p1, 1);
            p2 += __shfl_xor_sync(0xffffffffu, p2, 1);
            p3 += __shfl_xor_sync(0xffffffffu, p3, 1);
            float qa = b0 ? p1 : p0;           // head_l = b0
            float qb = b0 ? p3 : p2;           // head_l = 2 + b0
            qa += __shfl_xor_sync(0xffffffffu, qa, 2);
            qb += __shfl_xor_sync(0xffffffffu, qb, 2);
            rv[k] = b1 ? qb : qa;              // head_l = 2*b1 + b0
        }
        // node-select reduction stages
#pragma unroll
        for (int k = 0; k < 8; k++)
            rv[k] += __shfl_xor_sync(0xffffffffu, rv[k], 4);
        float sv[4];
#pragma unroll
        for (int j = 0; j < 4; j++) sv[j] = b2 ? rv[2 * j + 1] : rv[2 * j];
#pragma unroll
        for (int j = 0; j < 4; j++)
            sv[j] += __shfl_xor_sync(0xffffffffu, sv[j], 8);
        float tv0 = b3 ? sv[1] : sv[0];
        float tv1 = b3 ? sv[3] : sv[2];
        tv0 += __shfl_xor_sync(0xffffffffu, tv0, 16);
        tv1 += __shfl_xor_sync(0xffffffffu, tv1, 16);
        us[us_idx] = b4v ? tv1 : tv0;
        __syncthreads();

        // ---- finalize: warp w owns head w; lane = node
        {
            float u = us[lane * 9 + w];
            if (lane >= valid) u = -INFINITY;
            float mc = u;
#pragma unroll
            for (int off = 16; off; off >>= 1)
                mc = fmaxf(mc, __shfl_xor_sync(0xffffffffu, mc, off));
            float m_new = fmaxf(m_run, mc);
            float scale = __expf(m_run - m_new);
            float en = __expf(u - m_new);
            float ssum = en;
#pragma unroll
            for (int off = 16; off; off >>= 1)
                ssum += __shfl_xor_sync(0xffffffffu, ssum, off);
            s_run = fmaf(s_run, scale, ssum);
            m_run = m_new;
            es[w * 33 + lane] = en;
            if (lane == 0) sc[w] = scale;
        }
        __syncthreads();

        // ---- xa-phase: rescale + accumulate (x re-read; L1 hit)
        {
            float s0v = sc[grp * 4 + 0];
            float s1v = sc[grp * 4 + 1];
            float s2v = sc[grp * 4 + 2];
            float s3v = sc[grp * 4 + 3];
            acc[0].x *= s0v; acc[0].y *= s0v; acc[0].z *= s0v; acc[0].w *= s0v;
            acc[1].x *= s1v; acc[1].y *= s1v; acc[1].z *= s1v; acc[1].w *= s1v;
            acc[2].x *= s2v; acc[2].y *= s2v; acc[2].z *= s2v; acc[2].w *= s2v;
            acc[3].x *= s3v; acc[3].y *= s3v; acc[3].z *= s3v; acc[3].w *= s3v;
        }
#pragma unroll
        for (int k = 0; k < 8; k++) {
            int n = c0 + nodebase + k;
            if (n < hi) {
                float4 xv = xg[(size_t)n * 32 + lane];
                int nl = nodebase + k;
                float a0 = es[(grp * 4 + 0) * 33 + nl];
                float a1 = es[(grp * 4 + 1) * 33 + nl];
                float a2 = es[(grp * 4 + 2) * 33 + nl];
                float a3 = es[(grp * 4 + 3) * 33 + nl];
                acc[0].x = fmaf(a0, xv.x, acc[0].x); acc[0].y = fmaf(a0, xv.y, acc[0].y);
                acc[0].z = fmaf(a0, xv.z, acc[0].z); acc[0].w = fmaf(a0, xv.w, acc[0].w);
                acc[1].x = fmaf(a1, xv.x, acc[1].x); acc[1].y = fmaf(a1, xv.y, acc[1].y);
                acc[1].z = fmaf(a1, xv.z, acc[1].z); acc[1].w = fmaf(a1, xv.w, acc[1].w);
                acc[2].x = fmaf(a2, xv.x, acc[2].x); acc[2].y = fmaf(a2, xv.y, acc[2].y);
                acc[2].z = fmaf(a2, xv.z, acc[2].z); acc[2].w = fmaf(a2, xv.w, acc[2].w);
                acc[3].x = fmaf(a3, xv.x, acc[3].x); acc[3].y = fmaf(a3, xv.y, acc[3].y);
                acc[3].z = fmaf(a3, xv.z, acc[3].z); acc[3].w = fmaf(a3, xv.w, acc[3].w);
            }
        }
        __syncthreads();
    }

    // ---- slice m/s partials (warp w = head w)
    if (lane == 0) {
        int ims = (s * H + w) * B_GRAPHS + g;
        g_part_m[ims] = m_run;
        g_part_s[ims] = s_run;
    }

    // ---- cross-warp xa reduction: head h = grp*4+j summed over wi
#pragma unroll
    for (int j = 0; j < 4; j++)
        *(float4*)(buf + (((grp * 4 + wi) * 4 + j) * 32 + lane) * 4) = acc[j];
    __syncthreads();
    {
        int hg = w >> 2, hj = w & 3;     // warp w reduces head w
        float4 sum = z;
#pragma unroll
        for (int wwi = 0; wwi < 4; wwi++) {
            float4 v = *(const float4*)(buf + (((hg * 4 + wwi) * 4 + hj) * 32 + lane) * 4);
            sum.x += v.x; sum.y += v.y; sum.z += v.z; sum.w += v.w;
        }
        *(float4*)(g_part_xa + (size_t)((s * H + w) * B_GRAPHS + g) * DX + lane * 4) = sum;
    }
}

// ---------------------------------------------------------------------------
// Kernel 3: combine slice partials (softmax-weighted) + final projection.
// ---------------------------------------------------------------------------
__global__ __launch_bounds__(1024) void k_cf(const float* __restrict__ Wv,
                                             const float* __restrict__ qcoef,
                                             const float* __restrict__ Wf,
                                             float* __restrict__ out) {
    int g = blockIdx.x;
    int t = threadIdx.x;
    int h = t >> 7, e = t & 127;

    __shared__ float wgt[H][S_SLICES];
    __shared__ float inv_s[H];
    __shared__ float xa_s[H][DX];
    __shared__ float hpart[H][DV];
    __shared__ float tot[DV];

    if (e == 0) {
        float ms[S_SLICES], ss[S_SLICES];
#pragma unroll
        for (int i = 0; i < S_SLICES; i++) {
            int idx = (i * H + h) * B_GRAPHS + g;
            ms[i] = g_part_m[idx];
            ss[i] = g_part_s[idx];
        }
        float m = -INFINITY;
#pragma unroll
        for (int i = 0; i < S_SLICES; i++) m = fmaxf(m, ms[i]);
        float ssum = 0.0f;
#pragma unroll
        for (int i = 0; i < S_SLICES; i++) {
            float wi = (ms[i] == -INFINITY) ? 0.0f : __expf(ms[i] - m);
            wgt[h][i] = wi;
            ssum = fmaf(ss[i], wi, ssum);
        }
        inv_s[h] = 1.0f / (ssum + 1e-16f);
    }
    __syncthreads();

    {
        float accv = 0.0f;
#pragma unroll
        for (int i = 0; i < S_SLICES; i++)
            accv = fmaf(g_part_xa[(size_t)((i * H + h) * B_GRAPHS + g) * DX + e],
                        wgt[h][i], accv);
        xa_s[h][e] = accv * inv_s[h];
    }
    __syncthreads();

    if (t < 512) {
        int h2 = t >> 6, v = t & 63;
        float accv = qcoef[0] * g_query[(h2 * B_GRAPHS + g) * DV + v];
        const float* wv = Wv + h2 * DX * DV + v;
        const float* xa = xa_s[h2];
#pragma unroll 16
        for (int e2 = 0; e2 < DX; e2++) accv = fmaf(xa[e2], wv[e2 * DV], accv);
        hpart[h2][v] = accv;
    }
    __syncthreads();

    if (t < DV) {
        float sum = 0.0f;
#pragma unroll
        for (int hh = 0; hh < H; hh++) sum += hpart[hh][t];
        tot[t] = sum;
    }
    __syncthreads();

    if (t < DOUT) {
        float accv = 0.0f;
#pragma unroll 16
        for (int v2 = 0; v2 < DV; v2++)
            accv = fmaf(tot[v2], Wf[v2 * DOUT + t], accv);
        out[g * DOUT + t] = accv;
    }
}

// ---------------------------------------------------------------------------
extern "C" void kernel_launch(void* const* d_in, const int* in_sizes, int n_in,
                              void* d_out, int out_size) {
    const float* x       = (const float*)d_in[0];
    // d_in[1] = edge_index (unused by the reference math)
    const int*   batch   = (const int*)d_in[2];
    const float* context = (const float*)d_in[3];
    const float* Wq      = (const float*)d_in[4];
    const float* Wk      = (const float*)d_in[5];
    const float* Wv      = (const float*)d_in[6];
    const float* qcoef   = (const float*)d_in[7];
    const float* Wf      = (const float*)d_in[8];
    float* out = (float*)d_out;

    dim3 sg(S_SLICES, B_GRAPHS);
    k_qkq<<<H * 32, 256>>>(context, Wq, Wk);
    k_fused<<<sg, 256>>>(x, batch);
    k_cf<<<B_GRAPHS, 1024>>>(Wv, qcoef, Wf, out);
}

// round 9
// speedup vs baseline: 1.3970x; 1.0901x over previous
#include <cuda_runtime.h>
#include <math.h>

#define N_NODES 100000
#define B_GRAPHS 128
#define H 8
#define DC 256
#define DX 128   /* DE+4 */
#define DV 64
#define DOUT 124
#define S_SLICES 3

// ---- scratch (static device globals; no allocation) ----
__device__ __align__(16) float g_query[H * B_GRAPHS * DV];
__device__ __align__(16) float g_kq[H * B_GRAPHS * DX];
__device__ __align__(16) float g_part_xa[S_SLICES * H * B_GRAPHS * DX];
__device__ float g_part_m[S_SLICES * H * B_GRAPHS];
__device__ float g_part_s[S_SLICES * H * B_GRAPHS];

// ---------------------------------------------------------------------------
__device__ __forceinline__ int lb_batch(const int* __restrict__ batch, int key) {
    int lo = 0, hi = N_NODES;
    while (lo < hi) {
        int mid = (lo + hi) >> 1;
        if (__ldg(batch + mid) < key) lo = mid + 1; else hi = mid;
    }
    return lo;
}

// ---------------------------------------------------------------------------
// Kernel 1: query + kq. One block per graph, 1024 threads.
// ---------------------------------------------------------------------------
__global__ __launch_bounds__(1024) void k_qkq(const float* __restrict__ context,
                                              const float* __restrict__ Wq,
                                              const float* __restrict__ Wk) {
    int g = blockIdx.x;
    int t = threadIdx.x;

    __shared__ float ctx_s[DC];
    __shared__ float parts[2][H][DV];
    __shared__ __align__(16) float q_s[H][DV];

    if (t < DC) ctx_s[t] = context[g * DC + t];
    __syncthreads();

    {
        int h = t >> 7;
        int r = t & 127;
        int half = r >> 6;
        int v = r & 63;
        const float* wq = Wq + h * DC * DV + half * 128 * DV + v;
        const float* cs = ctx_s + half * 128;
        float a0 = 0.f, a1 = 0.f;
#pragma unroll 16
        for (int c = 0; c < 128; c += 2) {
            a0 = fmaf(cs[c],     wq[c * DV],       a0);
            a1 = fmaf(cs[c + 1], wq[(c + 1) * DV], a1);
        }
        parts[half][h][v] = a0 + a1;
    }
    __syncthreads();
    if (t < 512) {
        int h = t >> 6, v = t & 63;
        float q = parts[0][h][v] + parts[1][h][v];
        q_s[h][v] = q;
        g_query[(h * B_GRAPHS + g) * DV + v] = q;
    }
    __syncthreads();
    {
        int h = t >> 7, e = t & 127;
        const float4* wk = (const float4*)(Wk + (h * DX + e) * DV);
        const float4* qv = (const float4*)q_s[h];
        float a0 = 0.f, a1 = 0.f;
#pragma unroll
        for (int i = 0; i < 16; i += 2) {
            float4 wv = wk[i],     qq = qv[i];
            float4 w2 = wk[i + 1], q2 = qv[i + 1];
            a0 = fmaf(wv.x, qq.x, fmaf(wv.y, qq.y, fmaf(wv.z, qq.z, fmaf(wv.w, qq.w, a0))));
            a1 = fmaf(w2.x, q2.x, fmaf(w2.y, q2.y, fmaf(w2.z, q2.z, fmaf(w2.w, q2.w, a1))));
        }
        g_kq[(h * B_GRAPHS + g) * DX + e] = (a0 + a1) * 0.125f;   // 1/sqrt(64)
    }
}

// ---------------------------------------------------------------------------
// Kernel 2 (fused, head-split): warps 0-3 = heads 0-3, warps 4-7 = heads 4-7.
// ---------------------------------------------------------------------------
__global__ __launch_bounds__(256, 3) void k_fused(const float* __restrict__ x,
                                                  const int* __restrict__ batch) {
    const int s = blockIdx.x;
    const int g = blockIdx.y;
    const int t = threadIdx.x;
    const int w = t >> 5;
    const int lane = t & 31;
    const int grp = w >> 2;
    const int wi  = w & 3;

    const int b0 = lane & 1, b1 = (lane >> 1) & 1, b2 = (lane >> 2) & 1;
    const int b3 = (lane >> 3) & 1, b4v = (lane >> 4) & 1;

    __shared__ float us[32 * 9];
    __shared__ float es[H * 33];
    __shared__ float sc[H];
    __shared__ __align__(16) float buf[H * 4 * DX];

    int s0 = lb_batch(batch, g);
    int s1 = lb_batch(batch, g + 1);
    int len = s1 - s0;
    int per = (len + S_SLICES - 1) / S_SLICES;
    int lo = s0 + s * per;
    int hi = min(lo + per, s1);

    float4 kq[4];
#pragma unroll
    for (int j = 0; j < 4; j++)
        kq[j] = *(const float4*)(g_kq + ((grp * 4 + j) * B_GRAPHS + g) * DX + lane * 4);

    float4 acc[4];
#pragma unroll
    for (int j = 0; j < 4; j++) acc[j] = make_float4(0.f, 0.f, 0.f, 0.f);

    float m_run = -INFINITY, s_run = 0.0f;

    const float4* xg = (const float4*)x;
    const float4 z = make_float4(0.f, 0.f, 0.f, 0.f);
    const int nodebase = wi * 8;
    const int us_idx = (nodebase + 4 * b4v + 2 * b3 + b2) * 9 + grp * 4 + 2 * b1 + b0;

    for (int c0 = lo; c0 < hi; c0 += 32) {
        int valid = min(32, hi - c0);

        // ---- u-phase
        float rv[8];
#pragma unroll
        for (int k = 0; k < 8; k++) {
            int n = c0 + nodebase + k;
            float4 xv = (n < hi) ? xg[(size_t)n * 32 + lane] : z;
            float p0 = fmaf(kq[0].x, xv.x, fmaf(kq[0].y, xv.y, fmaf(kq[0].z, xv.z, kq[0].w * xv.w)));
            float p1 = fmaf(kq[1].x, xv.x, fmaf(kq[1].y, xv.y, fmaf(kq[1].z, xv.z, kq[1].w * xv.w)));
            float p2 = fmaf(kq[2].x, xv.x, fmaf(kq[2].y, xv.y, fmaf(kq[2].z, xv.z, kq[2].w * xv.w)));
            float p3 = fmaf(kq[3].x, xv.x, fmaf(kq[3].y, xv.y, fmaf(kq[3].z, xv.z, kq[3].w * xv.w)));
            p0 += __shfl_xor_sync(0xffffffffu, p0, 1);
            p1 += __shfl_xor_sync(0xffffffffu, p1, 1);
            p2 += __shfl_xor_sync(0xffffffffu, p2, 1);
            p3 += __shfl_xor_sync(0xffffffffu, p3, 1);
            float qa = b0 ? p1 : p0;
            float qb = b0 ? p3 : p2;
            qa += __shfl_xor_sync(0xffffffffu, qa, 2);
            qb += __shfl_xor_sync(0xffffffffu, qb, 2);
            rv[k] = b1 ? qb : qa;
        }
#pragma unroll
        for (int k = 0; k < 8; k++)
            rv[k] += __shfl_xor_sync(0xffffffffu, rv[k], 4);
        float sv[4];
#pragma unroll
        for (int j = 0; j < 4; j++) sv[j] = b2 ? rv[2 * j + 1] : rv[2 * j];
#pragma unroll
        for (int j = 0; j < 4; j++)
            sv[j] += __shfl_xor_sync(0xffffffffu, sv[j], 8);
        float tv0 = b3 ? sv[1] : sv[0];
        float tv1 = b3 ? sv[3] : sv[2];
        tv0 += __shfl_xor_sync(0xffffffffu, tv0, 16);
        tv1 += __shfl_xor_sync(0xffffffffu, tv1, 16);
        us[us_idx] = b4v ? tv1 : tv0;
        __syncthreads();

        // ---- finalize
        {
            float u = us[lane * 9 + w];
            if (lane >= valid) u = -INFINITY;
            float mc = u;
#pragma unroll
            for (int off = 16; off; off >>= 1)
                mc = fmaxf(mc, __shfl_xor_sync(0xffffffffu, mc, off));
            float m_new = fmaxf(m_run, mc);
            float scale = __expf(m_run - m_new);
            float en = __expf(u - m_new);
            float ssum = en;
#pragma unroll
            for (int off = 16; off; off >>= 1)
                ssum += __shfl_xor_sync(0xffffffffu, ssum, off);
            s_run = fmaf(s_run, scale, ssum);
            m_run = m_new;
            es[w * 33 + lane] = en;
            if (lane == 0) sc[w] = scale;
        }
        __syncthreads();

        // ---- xa-phase
        {
            float s0v = sc[grp * 4 + 0];
            float s1v = sc[grp * 4 + 1];
            float s2v = sc[grp * 4 + 2];
            float s3v = sc[grp * 4 + 3];
            acc[0].x *= s0v; acc[0].y *= s0v; acc[0].z *= s0v; acc[0].w *= s0v;
            acc[1].x *= s1v; acc[1].y *= s1v; acc[1].z *= s1v; acc[1].w *= s1v;
            acc[2].x *= s2v; acc[2].y *= s2v; acc[2].z *= s2v; acc[2].w *= s2v;
            acc[3].x *= s3v; acc[3].y *= s3v; acc[3].z *= s3v; acc[3].w *= s3v;
        }
#pragma unroll
        for (int k = 0; k < 8; k++) {
            int n = c0 + nodebase + k;
            if (n < hi) {
                float4 xv = xg[(size_t)n * 32 + lane];
                int nl = nodebase + k;
                float a0 = es[(grp * 4 + 0) * 33 + nl];
                float a1 = es[(grp * 4 + 1) * 33 + nl];
                float a2 = es[(grp * 4 + 2) * 33 + nl];
                float a3 = es[(grp * 4 + 3) * 33 + nl];
                acc[0].x = fmaf(a0, xv.x, acc[0].x); acc[0].y = fmaf(a0, xv.y, acc[0].y);
                acc[0].z = fmaf(a0, xv.z, acc[0].z); acc[0].w = fmaf(a0, xv.w, acc[0].w);
                acc[1].x = fmaf(a1, xv.x, acc[1].x); acc[1].y = fmaf(a1, xv.y, acc[1].y);
                acc[1].z = fmaf(a1, xv.z, acc[1].z); acc[1].w = fmaf(a1, xv.w, acc[1].w);
                acc[2].x = fmaf(a2, xv.x, acc[2].x); acc[2].y = fmaf(a2, xv.y, acc[2].y);
                acc[2].z = fmaf(a2, xv.z, acc[2].z); acc[2].w = fmaf(a2, xv.w, acc[2].w);
                acc[3].x = fmaf(a3, xv.x, acc[3].x); acc[3].y = fmaf(a3, xv.y, acc[3].y);
                acc[3].z = fmaf(a3, xv.z, acc[3].z); acc[3].w = fmaf(a3, xv.w, acc[3].w);
            }
        }
        __syncthreads();
    }

    if (lane == 0) {
        int ims = (s * H + w) * B_GRAPHS + g;
        g_part_m[ims] = m_run;
        g_part_s[ims] = s_run;
    }

#pragma unroll
    for (int j = 0; j < 4; j++)
        *(float4*)(buf + (((grp * 4 + wi) * 4 + j) * 32 + lane) * 4) = acc[j];
    __syncthreads();
    {
        int hg = w >> 2, hj = w & 3;
        float4 sum = z;
#pragma unroll
        for (int wwi = 0; wwi < 4; wwi++) {
            float4 v = *(const float4*)(buf + (((hg * 4 + wwi) * 4 + hj) * 32 + lane) * 4);
            sum.x += v.x; sum.y += v.y; sum.z += v.z; sum.w += v.w;
        }
        *(float4*)(g_part_xa + (size_t)((s * H + w) * B_GRAPHS + g) * DX + lane * 4) = sum;
    }
}

// ---------------------------------------------------------------------------
// Kernel 3: combine slice partials (softmax-weighted) + final projection.
// ---------------------------------------------------------------------------
__global__ __launch_bounds__(1024) void k_cf(const float* __restrict__ Wv,
                                             const float* __restrict__ qcoef,
                                             const float* __restrict__ Wf,
                                             float* __restrict__ out) {
    int g = blockIdx.x;
    int t = threadIdx.x;
    int h = t >> 7, e = t & 127;

    __shared__ float wgt[H][S_SLICES];
    __shared__ float inv_s[H];
    __shared__ float xa_s[H][DX];
    __shared__ float hpart[H][DV];
    __shared__ float tot[DV];

    if (e == 0) {
        float ms[S_SLICES], ss[S_SLICES];
#pragma unroll
        for (int i = 0; i < S_SLICES; i++) {
            int idx = (i * H + h) * B_GRAPHS + g;
            ms[i] = g_part_m[idx];
            ss[i] = g_part_s[idx];
        }
        float m = -INFINITY;
#pragma unroll
        for (int i = 0; i < S_SLICES; i++) m = fmaxf(m, ms[i]);
        float ssum = 0.0f;
#pragma unroll
        for (int i = 0; i < S_SLICES; i++) {
            float wi = (ms[i] == -INFINITY) ? 0.0f : __expf(ms[i] - m);
            wgt[h][i] = wi;
            ssum = fmaf(ss[i], wi, ssum);
        }
        inv_s[h] = 1.0f / (ssum + 1e-16f);
    }
    __syncthreads();

    {
        float accv = 0.0f;
#pragma unroll
        for (int i = 0; i < S_SLICES; i++)
            accv = fmaf(g_part_xa[(size_t)((i * H + h) * B_GRAPHS + g) * DX + e],
                        wgt[h][i], accv);
        xa_s[h][e] = accv * inv_s[h];
    }
    __syncthreads();

    if (t < 512) {
        int h2 = t >> 6, v = t & 63;
        float accv = qcoef[0] * g_query[(h2 * B_GRAPHS + g) * DV + v];
        const float* wv = Wv + h2 * DX * DV + v;
        const float* xa = xa_s[h2];
#pragma unroll 16
        for (int e2 = 0; e2 < DX; e2++) accv = fmaf(xa[e2], wv[e2 * DV], accv);
        hpart[h2][v] = accv;
    }
    __syncthreads();

    if (t < DV) {
        float sum = 0.0f;
#pragma unroll
        for (int hh = 0; hh < H; hh++) sum += hpart[hh][t];
        tot[t] = sum;
    }
    __syncthreads();

    if (t < DOUT) {
        float accv = 0.0f;
#pragma unroll 16
        for (int v2 = 0; v2 < DV; v2++)
            accv = fmaf(tot[v2], Wf[v2 * DOUT + t], accv);
        out[g * DOUT + t] = accv;
    }
}

// ---------------------------------------------------------------------------
extern "C" void kernel_launch(void* const* d_in, const int* in_sizes, int n_in,
                              void* d_out, int out_size) {
    const float* x       = (const float*)d_in[0];
    // d_in[1] = edge_index (unused by the reference math)
    const int*   batch   = (const int*)d_in[2];
    const float* context = (const float*)d_in[3];
    const float* Wq      = (const float*)d_in[4];
    const float* Wk      = (const float*)d_in[5];
    const float* Wv      = (const float*)d_in[6];
    const float* qcoef   = (const float*)d_in[7];
    const float* Wf      = (const float*)d_in[8];
    float* out = (float*)d_out;

    dim3 sg(S_SLICES, B_GRAPHS);
    k_qkq<<<B_GRAPHS, 1024>>>(context, Wq, Wk);
    k_fused<<<sg, 256>>>(x, batch);
    k_cf<<<B_GRAPHS, 1024>>>(Wv, qcoef, Wf, out);
}

// round 10
// speedup vs baseline: 1.5999x; 1.1452x over previous
#include <cuda_runtime.h>
#include <math.h>

#define N_NODES 100000
#define B_GRAPHS 128
#define H 8
#define DC 256
#define DX 128   /* DE+4 */
#define DV 64
#define DOUT 124
#define S_SLICES 3

// ---- scratch (static device globals; no allocation) ----
__device__ __align__(16) float g_query[H * B_GRAPHS * DV];
__device__ __align__(16) float g_kq[H * B_GRAPHS * DX];
__device__ __align__(16) float g_part_xa[S_SLICES * H * B_GRAPHS * DX];
__device__ float g_part_m[S_SLICES * H * B_GRAPHS];
__device__ float g_part_s[S_SLICES * H * B_GRAPHS];

// ---------------------------------------------------------------------------
__device__ __forceinline__ int lb_batch(const int* __restrict__ batch, int key) {
    int lo = 0, hi = N_NODES;
    while (lo < hi) {
        int mid = (lo + hi) >> 1;
        if (__ldg(batch + mid) < key) lo = mid + 1; else hi = mid;
    }
    return lo;
}

// ---------------------------------------------------------------------------
// Kernel 1: query + kq. Block = (h, graph-octet): grid H*16, 1024 threads.
// Weights read once per block as float4, shared across 8 graph-lanes.
// Phase A: thread = (gb, v4, ksplit): float4 acc over 32 c's; smem reduce.
// Phase B: thread = (gb, e): two-chain float4 row dot over DV.
// ---------------------------------------------------------------------------
__global__ __launch_bounds__(1024) void k_qkq(const float* __restrict__ context,
                                              const float* __restrict__ Wq,
                                              const float* __restrict__ Wk) {
    const int h  = blockIdx.x >> 4;
    const int go = blockIdx.x & 15;         // graph octet: graphs go*8 .. go*8+7
    const int t = threadIdx.x;
    const int w = t >> 5;
    const int lane = t & 31;

    __shared__ float ctx_s[8][260];                    // padded (bank spread)
    __shared__ __align__(16) float parts[8][8][68];    // [ksplit][gb][v] padded
    __shared__ __align__(16) float q_s[8][68];         // [gb][v] padded

    // load 8 contexts
    for (int i = t; i < 8 * DC; i += 1024)
        ctx_s[i >> 8][i & 255] = context[(go * 8 + (i >> 8)) * DC + (i & 255)];
    __syncthreads();

    // ---- phase A: q[gb, v] = ctx[gb] . Wq[h][:, v]
    {
        const int gb = lane & 7;
        const int j  = lane >> 3;            // 0..3
        const int v4 = w & 15;               // 0..15
        const int ks = ((w >> 4) << 2) | j;  // 0..7
        const int c0 = ks * 32;

        const float4* wq4 = (const float4*)(Wq + h * DC * DV) + v4;
        const float* cs = &ctx_s[gb][c0];
        float4 acc = make_float4(0.f, 0.f, 0.f, 0.f);
#pragma unroll 8
        for (int c = 0; c < 32; c++) {
            float cv = cs[c];
            float4 wv = wq4[(size_t)(c0 + c) * 16];
            acc.x = fmaf(cv, wv.x, acc.x);
            acc.y = fmaf(cv, wv.y, acc.y);
            acc.z = fmaf(cv, wv.z, acc.z);
            acc.w = fmaf(cv, wv.w, acc.w);
        }
        *(float4*)(&parts[ks][gb][v4 * 4]) = acc;
    }
    __syncthreads();

    // reduce ksplit + write q
    if (t < 512) {
        int gb = t >> 6, v = t & 63;
        float q = 0.f;
#pragma unroll
        for (int ks = 0; ks < 8; ks++) q += parts[ks][gb][v];
        q_s[gb][v] = q;
        g_query[(h * B_GRAPHS + go * 8 + gb) * DV + v] = q;
    }
    __syncthreads();

    // ---- phase B: kq[gb, e] = (Wk[h][e,:] . q[gb]) / 8
    {
        const int gb = t & 7;
        const int e  = t >> 3;               // 0..127
        const float4* wk4 = (const float4*)(Wk + (h * DX + e) * DV);
        const float4* qv  = (const float4*)(&q_s[gb][0]);
        float a0 = 0.f, a1 = 0.f;
#pragma unroll
        for (int i = 0; i < 16; i += 2) {
            float4 wv = wk4[i],     qq = qv[i];
            float4 w2 = wk4[i + 1], q2 = qv[i + 1];
            a0 = fmaf(wv.x, qq.x, fmaf(wv.y, qq.y, fmaf(wv.z, qq.z, fmaf(wv.w, qq.w, a0))));
            a1 = fmaf(w2.x, q2.x, fmaf(w2.y, q2.y, fmaf(w2.z, q2.z, fmaf(w2.w, q2.w, a1))));
        }
        g_kq[(h * B_GRAPHS + go * 8 + gb) * DX + e] = (a0 + a1) * 0.125f;  // 1/sqrt(64)
    }
}

// ---------------------------------------------------------------------------
// Kernel 2 (fused, head-split): warps 0-3 = heads 0-3, warps 4-7 = heads 4-7.
// ---------------------------------------------------------------------------
__global__ __launch_bounds__(256, 3) void k_fused(const float* __restrict__ x,
                                                  const int* __restrict__ batch) {
    const int s = blockIdx.x;
    const int g = blockIdx.y;
    const int t = threadIdx.x;
    const int w = t >> 5;
    const int lane = t & 31;
    const int grp = w >> 2;
    const int wi  = w & 3;

    const int b0 = lane & 1, b1 = (lane >> 1) & 1, b2 = (lane >> 2) & 1;
    const int b3 = (lane >> 3) & 1, b4v = (lane >> 4) & 1;

    __shared__ float us[32 * 9];
    __shared__ float es[H * 33];
    __shared__ float sc[H];
    __shared__ __align__(16) float buf[H * 4 * DX];

    int s0 = lb_batch(batch, g);
    int s1 = lb_batch(batch, g + 1);
    int len = s1 - s0;
    int per = (len + S_SLICES - 1) / S_SLICES;
    int lo = s0 + s * per;
    int hi = min(lo + per, s1);

    float4 kq[4];
#pragma unroll
    for (int j = 0; j < 4; j++)
        kq[j] = *(const float4*)(g_kq + ((grp * 4 + j) * B_GRAPHS + g) * DX + lane * 4);

    float4 acc[4];
#pragma unroll
    for (int j = 0; j < 4; j++) acc[j] = make_float4(0.f, 0.f, 0.f, 0.f);

    float m_run = -INFINITY, s_run = 0.0f;

    const float4* xg = (const float4*)x;
    const float4 z = make_float4(0.f, 0.f, 0.f, 0.f);
    const int nodebase = wi * 8;
    const int us_idx = (nodebase + 4 * b4v + 2 * b3 + b2) * 9 + grp * 4 + 2 * b1 + b0;

    for (int c0 = lo; c0 < hi; c0 += 32) {
        int valid = min(32, hi - c0);

        // ---- u-phase
        float rv[8];
#pragma unroll
        for (int k = 0; k < 8; k++) {
            int n = c0 + nodebase + k;
            float4 xv = (n < hi) ? xg[(size_t)n * 32 + lane] : z;
            float p0 = fmaf(kq[0].x, xv.x, fmaf(kq[0].y, xv.y, fmaf(kq[0].z, xv.z, kq[0].w * xv.w)));
            float p1 = fmaf(kq[1].x, xv.x, fmaf(kq[1].y, xv.y, fmaf(kq[1].z, xv.z, kq[1].w * xv.w)));
            float p2 = fmaf(kq[2].x, xv.x, fmaf(kq[2].y, xv.y, fmaf(kq[2].z, xv.z, kq[2].w * xv.w)));
            float p3 = fmaf(kq[3].x, xv.x, fmaf(kq[3].y, xv.y, fmaf(kq[3].z, xv.z, kq[3].w * xv.w)));
            p0 += __shfl_xor_sync(0xffffffffu, p0, 1);
            p1 += __shfl_xor_sync(0xffffffffu, p1, 1);
            p2 += __shfl_xor_sync(0xffffffffu, p2, 1);
            p3 += __shfl_xor_sync(0xffffffffu, p3, 1);
            float qa = b0 ? p1 : p0;
            float qb = b0 ? p3 : p2;
            qa += __shfl_xor_sync(0xffffffffu, qa, 2);
            qb += __shfl_xor_sync(0xffffffffu, qb, 2);
            rv[k] = b1 ? qb : qa;
        }
#pragma unroll
        for (int k = 0; k < 8; k++)
            rv[k] += __shfl_xor_sync(0xffffffffu, rv[k], 4);
        float sv[4];
#pragma unroll
        for (int j = 0; j < 4; j++) sv[j] = b2 ? rv[2 * j + 1] : rv[2 * j];
#pragma unroll
        for (int j = 0; j < 4; j++)
            sv[j] += __shfl_xor_sync(0xffffffffu, sv[j], 8);
        float tv0 = b3 ? sv[1] : sv[0];
        float tv1 = b3 ? sv[3] : sv[2];
        tv0 += __shfl_xor_sync(0xffffffffu, tv0, 16);
        tv1 += __shfl_xor_sync(0xffffffffu, tv1, 16);
        us[us_idx] = b4v ? tv1 : tv0;
        __syncthreads();

        // ---- finalize
        {
            float u = us[lane * 9 + w];
            if (lane >= valid) u = -INFINITY;
            float mc = u;
#pragma unroll
            for (int off = 16; off; off >>= 1)
                mc = fmaxf(mc, __shfl_xor_sync(0xffffffffu, mc, off));
            float m_new = fmaxf(m_run, mc);
            float scale = __expf(m_run - m_new);
            float en = __expf(u - m_new);
            float ssum = en;
#pragma unroll
            for (int off = 16; off; off >>= 1)
                ssum += __shfl_xor_sync(0xffffffffu, ssum, off);
            s_run = fmaf(s_run, scale, ssum);
            m_run = m_new;
            es[w * 33 + lane] = en;
            if (lane == 0) sc[w] = scale;
        }
        __syncthreads();

        // ---- xa-phase
        {
            float s0v = sc[grp * 4 + 0];
            float s1v = sc[grp * 4 + 1];
            float s2v = sc[grp * 4 + 2];
            float s3v = sc[grp * 4 + 3];
            acc[0].x *= s0v; acc[0].y *= s0v; acc[0].z *= s0v; acc[0].w *= s0v;
            acc[1].x *= s1v; acc[1].y *= s1v; acc[1].z *= s1v; acc[1].w *= s1v;
            acc[2].x *= s2v; acc[2].y *= s2v; acc[2].z *= s2v; acc[2].w *= s2v;
            acc[3].x *= s3v; acc[3].y *= s3v; acc[3].z *= s3v; acc[3].w *= s3v;
        }
#pragma unroll
        for (int k = 0; k < 8; k++) {
            int n = c0 + nodebase + k;
            if (n < hi) {
                float4 xv = xg[(size_t)n * 32 + lane];
                int nl = nodebase + k;
                float a0 = es[(grp * 4 + 0) * 33 + nl];
                float a1 = es[(grp * 4 + 1) * 33 + nl];
                float a2 = es[(grp * 4 + 2) * 33 + nl];
                float a3 = es[(grp * 4 + 3) * 33 + nl];
                acc[0].x = fmaf(a0, xv.x, acc[0].x); acc[0].y = fmaf(a0, xv.y, acc[0].y);
                acc[0].z = fmaf(a0, xv.z, acc[0].z); acc[0].w = fmaf(a0, xv.w, acc[0].w);
                acc[1].x = fmaf(a1, xv.x, acc[1].x); acc[1].y = fmaf(a1, xv.y, acc[1].y);
                acc[1].z = fmaf(a1, xv.z, acc[1].z); acc[1].w = fmaf(a1, xv.w, acc[1].w);
                acc[2].x = fmaf(a2, xv.x, acc[2].x); acc[2].y = fmaf(a2, xv.y, acc[2].y);
                acc[2].z = fmaf(a2, xv.z, acc[2].z); acc[2].w = fmaf(a2, xv.w, acc[2].w);
                acc[3].x = fmaf(a3, xv.x, acc[3].x); acc[3].y = fmaf(a3, xv.y, acc[3].y);
                acc[3].z = fmaf(a3, xv.z, acc[3].z); acc[3].w = fmaf(a3, xv.w, acc[3].w);
            }
        }
        __syncthreads();
    }

    if (lane == 0) {
        int ims = (s * H + w) * B_GRAPHS + g;
        g_part_m[ims] = m_run;
        g_part_s[ims] = s_run;
    }

#pragma unroll
    for (int j = 0; j < 4; j++)
        *(float4*)(buf + (((grp * 4 + wi) * 4 + j) * 32 + lane) * 4) = acc[j];
    __syncthreads();
    {
        int hg = w >> 2, hj = w & 3;
        float4 sum = z;
#pragma unroll
        for (int wwi = 0; wwi < 4; wwi++) {
            float4 v = *(const float4*)(buf + (((hg * 4 + wwi) * 4 + hj) * 32 + lane) * 4);
            sum.x += v.x; sum.y += v.y; sum.z += v.z; sum.w += v.w;
        }
        *(float4*)(g_part_xa + (size_t)((s * H + w) * B_GRAPHS + g) * DX + lane * 4) = sum;
    }
}

// ---------------------------------------------------------------------------
// Kernel 3: combine slice partials (softmax-weighted) + final projection.
// ---------------------------------------------------------------------------
__global__ __launch_bounds__(1024) void k_cf(const float* __restrict__ Wv,
                                             const float* __restrict__ qcoef,
                                             const float* __restrict__ Wf,
                                             float* __restrict__ out) {
    int g = blockIdx.x;
    int t = threadIdx.x;
    int h = t >> 7, e = t & 127;

    __shared__ float wgt[H][S_SLICES];
    __shared__ float inv_s[H];
    __shared__ float xa_s[H][DX];
    __shared__ float hpart[H][DV];
    __shared__ float tot[DV];

    if (e == 0) {
        float ms[S_SLICES], ss[S_SLICES];
#pragma unroll
        for (int i = 0; i < S_SLICES; i++) {
            int idx = (i * H + h) * B_GRAPHS + g;
            ms[i] = g_part_m[idx];
            ss[i] = g_part_s[idx];
        }
        float m = -INFINITY;
#pragma unroll
        for (int i = 0; i < S_SLICES; i++) m = fmaxf(m, ms[i]);
        float ssum = 0.0f;
#pragma unroll
        for (int i = 0; i < S_SLICES; i++) {
            float wi = (ms[i] == -INFINITY) ? 0.0f : __expf(ms[i] - m);
            wgt[h][i] = wi;
            ssum = fmaf(ss[i], wi, ssum);
        }
        inv_s[h] = 1.0f / (ssum + 1e-16f);
    }
    __syncthreads();

    {
        float accv = 0.0f;
#pragma unroll
        for (int i = 0; i < S_SLICES; i++)
            accv = fmaf(g_part_xa[(size_t)((i * H + h) * B_GRAPHS + g) * DX + e],
                        wgt[h][i], accv);
        xa_s[h][e] = accv * inv_s[h];
    }
    __syncthreads();

    if (t < 512) {
        int h2 = t >> 6, v = t & 63;
        float accv = qcoef[0] * g_query[(h2 * B_GRAPHS + g) * DV + v];
        const float* wv = Wv + h2 * DX * DV + v;
        const float* xa = xa_s[h2];
#pragma unroll 16
        for (int e2 = 0; e2 < DX; e2++) accv = fmaf(xa[e2], wv[e2 * DV], accv);
        hpart[h2][v] = accv;
    }
    __syncthreads();

    if (t < DV) {
        float sum = 0.0f;
#pragma unroll
        for (int hh = 0; hh < H; hh++) sum += hpart[hh][t];
        tot[t] = sum;
    }
    __syncthreads();

    if (t < DOUT) {
        float accv = 0.0f;
#pragma unroll 16
        for (int v2 = 0; v2 < DV; v2++)
            accv = fmaf(tot[v2], Wf[v2 * DOUT + t], accv);
        out[g * DOUT + t] = accv;
    }
}

// ---------------------------------------------------------------------------
extern "C" void kernel_launch(void* const* d_in, const int* in_sizes, int n_in,
                              void* d_out, int out_size) {
    const float* x       = (const float*)d_in[0];
    // d_in[1] = edge_index (unused by the reference math)
    const int*   batch   = (const int*)d_in[2];
    const float* context = (const float*)d_in[3];
    const float* Wq      = (const float*)d_in[4];
    const float* Wk      = (const float*)d_in[5];
    const float* Wv      = (const float*)d_in[6];
    const float* qcoef   = (const float*)d_in[7];
    const float* Wf      = (const float*)d_in[8];
    float* out = (float*)d_out;

    dim3 sg(S_SLICES, B_GRAPHS);
    k_qkq<<<H * 16, 1024>>>(context, Wq, Wk);
    k_fused<<<sg, 256>>>(x, batch);
    k_cf<<<B_GRAPHS, 1024>>>(Wv, qcoef, Wf, out);
}